// round 13
// baseline (speedup 1.0000x reference)
#include <cuda_runtime.h>
#include <cstdint>

// Problem constants
constexpr int B_  = 256;
constexpr int T_  = 512;
constexpr int H_  = 256;
constexpr int MTOT = B_ * T_;
constexpr size_t MH = (size_t)MTOT * H_;

// Scan decomposition: 32 batch groups of 8 rows x 8 column CTAs = 256 CTAs.
// ~2 CTAs co-resident per SM -> hardware-scheduled latency hiding.
constexpr int NC  = 8;
constexpr int HC  = 32;
constexpr int NG  = 32;   // batch groups
constexpr int GR  = 8;    // rows per group
constexpr int AST = 264;  // asm row stride (floats): 1056B, 16B-aligned, bank-shifted

// ---------------- device scratch ----------------
__device__ float g_xp[3 * MH];                 // projected inputs [gate][m][H]
__device__ float g_h [2][NG][GR][H_];          // pre-decayed h, double-buffered
__device__ float g_rh[2][NG][GR][H_];          // r*h_dec, double-buffered
__device__ unsigned g_cnt_rh[NG][NC][32];      // per-producer flags (128B padded)
__device__ unsigned g_cnt_h [NG][NC][32];

// ---------------- f32x2 helpers ----------------
__device__ __forceinline__ unsigned long long pack2(float a, float b) {
    unsigned long long r;
    asm("mov.b64 %0, {%1,%2};" : "=l"(r) : "f"(a), "f"(b));
    return r;
}
__device__ __forceinline__ void fma2(unsigned long long& d, unsigned long long a, unsigned long long b) {
    asm("fma.rn.f32x2 %0, %1, %2, %0;" : "+l"(d) : "l"(a), "l"(b));
}
__device__ __forceinline__ unsigned long long add2(unsigned long long a, unsigned long long b) {
    unsigned long long r;
    asm("add.rn.f32x2 %0, %1, %2;" : "=l"(r) : "l"(a), "l"(b));
    return r;
}
__device__ __forceinline__ float fold2(unsigned long long v) {
    float lo, hi;
    asm("mov.b64 {%0,%1}, %2;" : "=f"(lo), "=f"(hi) : "l"(v));
    return lo + hi;
}

__device__ __forceinline__ float sigmoid_(float v) {
    float e = __expf(-v);
    return __fdividef(1.f, 1.f + e);
}
__device__ __forceinline__ float tanh_(float v) {
    float e = __expf(2.f * v);
    return __fdividef(e - 1.f, e + 1.f);
}

// ---------------- flag primitives (champion style) ----------------
__device__ __forceinline__ void set_flag(unsigned* f, unsigned v) {
    asm volatile("st.release.gpu.global.u32 [%0], %1;" :: "l"(f), "r"(v) : "memory");
}
__device__ __forceinline__ void poll_ge(const unsigned* f, unsigned need) {
    unsigned v;
    do {
        asm volatile("ld.acquire.gpu.global.u32 %0, [%1];" : "=r"(v) : "l"(f) : "memory");
    } while (v < need);
}

// ================= projection GEMM (proven, ~571us) =================
__global__ __launch_bounds__(256) void proj_kernel(
    const float* __restrict__ x,
    const float* __restrict__ Wz, const float* __restrict__ Wr, const float* __restrict__ Wh,
    const float* __restrict__ bz, const float* __restrict__ br, const float* __restrict__ bh)
{
    __shared__ float As[32 * 132];
    __shared__ float Bs[32 * 64];

    const int g = blockIdx.z;
    const float* W    = (g == 0) ? Wz : (g == 1) ? Wr : Wh;
    const float* bias = (g == 0) ? bz : (g == 1) ? br : bh;
    float* out = g_xp + (size_t)g * MH;

    const int mtile = blockIdx.x * 128;
    const int ntile = blockIdx.y * 64;
    const int tid = threadIdx.x;
    const int tm = tid >> 4;
    const int tn = tid & 15;

    float acc[8][4] = {};

    for (int kc = 0; kc < 128; kc += 32) {
        __syncthreads();
        #pragma unroll
        for (int it = 0; it < 4; ++it) {
            int idx = tid + it * 256;
            int m = idx >> 3, c4 = idx & 7;
            float4 v = *(const float4*)&x[(size_t)(mtile + m) * 128 + kc + c4 * 4];
            As[(c4 * 4 + 0) * 132 + m] = v.x;
            As[(c4 * 4 + 1) * 132 + m] = v.y;
            As[(c4 * 4 + 2) * 132 + m] = v.z;
            As[(c4 * 4 + 3) * 132 + m] = v.w;
        }
        #pragma unroll
        for (int it = 0; it < 2; ++it) {
            int idx = tid + it * 256;
            int kk = idx >> 4, n4 = idx & 15;
            float4 v = *(const float4*)&W[(size_t)(kc + kk) * 256 + ntile + n4 * 4];
            *(float4*)&Bs[kk * 64 + n4 * 4] = v;
        }
        __syncthreads();

        #pragma unroll
        for (int kk = 0; kk < 32; ++kk) {
            float4 a0 = *(const float4*)&As[kk * 132 + tm * 8];
            float4 a1 = *(const float4*)&As[kk * 132 + tm * 8 + 4];
            float4 bv = *(const float4*)&Bs[kk * 64 + tn * 4];
            float a[8] = {a0.x, a0.y, a0.z, a0.w, a1.x, a1.y, a1.z, a1.w};
            #pragma unroll
            for (int i = 0; i < 8; i++) {
                acc[i][0] += a[i] * bv.x;
                acc[i][1] += a[i] * bv.y;
                acc[i][2] += a[i] * bv.z;
                acc[i][3] += a[i] * bv.w;
            }
        }
    }

    float4 bb = *(const float4*)&bias[ntile + tn * 4];
    #pragma unroll
    for (int i = 0; i < 8; i++) {
        float4 o = make_float4(acc[i][0] + bb.x, acc[i][1] + bb.y,
                               acc[i][2] + bb.z, acc[i][3] + bb.w);
        *(float4*)&out[(size_t)(mtile + tm * 8 + i) * 256 + ntile + tn * 4] = o;
    }
}

// ================= reset: zero flags + g_h buffer 0 =================
__global__ void reset_kernel() {
    int i = blockIdx.x * 256 + threadIdx.x;
    if (i < NG * GR * H_) ((float*)g_h)[i] = 0.f;     // g_h[0] = 0 (65536 floats)
    if (i < NG * NC * 32) {
        ((unsigned*)g_cnt_rh)[i] = 0;
        ((unsigned*)g_cnt_h)[i]  = 0;
    }
}

// ================= persistent recurrent scan (champion structure, GR=8) ======
// CTA (grp, cg) owns columns [32cg, 32cg+32) x 8 batch rows. Warp w's k-slice
// is [32w,32w+32); its gather source is CTA w. Thread (w,l) finalizes
// (row w, col j). 2 CTAs/SM co-reside; hardware hides poll/gather stalls.
__global__ __launch_bounds__(256) void scan_kernel(
    const float* __restrict__ Uz, const float* __restrict__ Ur, const float* __restrict__ Uh,
    const float* __restrict__ hdecay, float* __restrict__ out)
{
    extern __shared__ float smdyn[];
    float* asm_h  = smdyn;                              // [8][264]  8.25KB
    float* asm_rh = smdyn + GR * AST;                   // [8][264]  8.25KB
    unsigned long long* red_z = (unsigned long long*)(smdyn + 2 * GR * AST); // [8][8][32] 16KB
    unsigned long long* red_r = red_z + 2048;                                // 16KB

    const int tid = threadIdx.x;
    const int w = tid >> 5;          // warp -> k block [32w,32w+32), source CTA w
    const int l = tid & 31;
    const int grp = blockIdx.x >> 3;
    const int cg  = blockIdx.x & 7;
    const int j = cg * HC + l;
    const int brow = grp * GR + w;   // global batch row this thread finalizes

    // weights: packed f32x2 over k-pairs
    unsigned long long uz2[16], ur2[16], uh2[16];
    #pragma unroll
    for (int p = 0; p < 16; ++p) {
        int k = w * 32 + 2 * p;
        uz2[p] = pack2(Uz[(size_t)k * H_ + j], Uz[(size_t)(k + 1) * H_ + j]);
        ur2[p] = pack2(Ur[(size_t)k * H_ + j], Ur[(size_t)(k + 1) * H_ + j]);
        uh2[p] = pack2(Uh[(size_t)k * H_ + j], Uh[(size_t)(k + 1) * H_ + j]);
    }

    const unsigned* frh = &g_cnt_rh[grp][w][0];   // source CTA w's flags
    const unsigned* fh  = &g_cnt_h [grp][w][0];
    unsigned* myfrh = &g_cnt_rh[grp][cg][0];      // own flags
    unsigned* myfh  = &g_cnt_h [grp][cg][0];

    // gather mapping: lane l -> row l>>2, two float4 blocks at (l&3)*2
    const int grow = l >> 2;
    const int gblk = (l & 3) * 2;

    // x projections for t=0
    const size_t mbase = (size_t)brow * T_;
    float xz = g_xp[mbase * 256 + j];
    float xr = g_xp[MH + mbase * 256 + j];
    float xh = g_xp[2 * MH + mbase * 256 + j];

    for (int t = 0; t < T_; ++t) {
        const int p = t & 1;
        const size_t m = mbase + t;
        const bool more = (t + 1 < T_);
        const float decn = more ? hdecay[m + 1] : 0.f;

        // ---- A: wait for source CTA w's h(t), gather slice into smem ----
        poll_ge(fh, (unsigned)t);
        {
            const float4* src = (const float4*)&g_h[p][grp][grow][w * 32] + gblk;
            float4 v0 = __ldcg(src), v1 = __ldcg(src + 1);
            float4* dst = (float4*)&asm_h[grow * AST + w * 32] + gblk;
            dst[0] = v0; dst[1] = v1;
        }
        __syncwarp();

        // ---- B: merged z+r GEMM (one pass over asm_h, 8 rows) ----
        #pragma unroll 1
        for (int b = 0; b < GR; ++b) {
            unsigned long long az0 = 0, az1 = 0, ar0 = 0, ar1 = 0;
            const float* hrow = &asm_h[b * AST + w * 32];
            #pragma unroll
            for (int q = 0; q < 8; ++q) {
                ulonglong2 hv = *(const ulonglong2*)(hrow + q * 4);
                fma2(az0, hv.x, uz2[2 * q]);
                fma2(az1, hv.y, uz2[2 * q + 1]);
                fma2(ar0, hv.x, ur2[2 * q]);
                fma2(ar1, hv.y, ur2[2 * q + 1]);
            }
            red_z[(w * 8 + b) * 32 + l] = add2(az0, az1);
            red_r[(w * 8 + b) * 32 + l] = add2(ar0, ar1);
        }
        __syncthreads();   // S1: partials + all h staging visible CTA-wide

        // ---- C: r reduce, publish rh row w (col stripe cg) ----
        const float hd = asm_h[w * AST + j];
        {
            unsigned long long s = 0;
            #pragma unroll
            for (int ww = 0; ww < 8; ++ww) s = add2(s, red_r[(ww * 8 + w) * 32 + l]);
            float r = sigmoid_(fold2(s) + xr);
            __stcg(&g_rh[p][grp][w][j], r * hd);
        }
        __syncthreads();   // S2: all rh stores issued before release
        if (tid == 0) set_flag(myfrh, (unsigned)(t + 1));

        // ---- D: z reduce (fills rh propagation latency) ----
        float zv;
        {
            unsigned long long s = 0;
            #pragma unroll
            for (int ww = 0; ww < 8; ++ww) s = add2(s, red_z[(ww * 8 + w) * 32 + l]);
            zv = sigmoid_(fold2(s) + xz);
        }

        // ---- E: wait for source CTA w's rh, gather slice ----
        poll_ge(frh, (unsigned)(t + 1));
        {
            const float4* src = (const float4*)&g_rh[p][grp][grow][w * 32] + gblk;
            float4 v0 = __ldcg(src), v1 = __ldcg(src + 1);
            float4* dst = (float4*)&asm_rh[grow * AST + w * 32] + gblk;
            dst[0] = v0; dst[1] = v1;
        }
        __syncwarp();

        // ---- F: h GEMM (partials reuse red_r; safe past S2) ----
        #pragma unroll 1
        for (int b = 0; b < GR; ++b) {
            unsigned long long ah0 = 0, ah1 = 0;
            const float* hrow = &asm_rh[b * AST + w * 32];
            #pragma unroll
            for (int q = 0; q < 8; ++q) {
                ulonglong2 hv = *(const ulonglong2*)(hrow + q * 4);
                fma2(ah0, hv.x, uh2[2 * q]);
                fma2(ah1, hv.y, uh2[2 * q + 1]);
            }
            red_r[(w * 8 + b) * 32 + l] = add2(ah0, ah1);
        }
        __syncthreads();   // S3

        // ---- H: h reduce, combine, publish pre-decayed h(t+1) ----
        float h;
        {
            unsigned long long s = 0;
            #pragma unroll
            for (int ww = 0; ww < 8; ++ww) s = add2(s, red_r[(ww * 8 + w) * 32 + l]);
            float hp = tanh_(fold2(s) + xh);
            h = (1.f - zv) * hd + zv * hp;
            if (more) __stcg(&g_h[(t + 1) & 1][grp][w][j], h * decn);
        }
        __syncthreads();   // S4: all h stores issued before release
        if (more && tid == 0) set_flag(myfh, (unsigned)(t + 1));

        // ---- I: output + next-step x prefetch (x consumed; safe to reload) ----
        out[m * 256 + j] = h;
        if (more) {
            xz = g_xp[(m + 1) * 256 + j];
            xr = g_xp[MH + (m + 1) * 256 + j];
            xh = g_xp[2 * MH + (m + 1) * 256 + j];
        }
    }
}

// ================= launch =================
extern "C" void kernel_launch(void* const* d_in, const int* /*in_sizes*/, int /*n_in*/,
                              void* d_out, int /*out_size*/)
{
    const float* x      = (const float*)d_in[0];
    const float* hdecay = (const float*)d_in[1];
    const float* Wr = (const float*)d_in[2];
    const float* Wz = (const float*)d_in[3];
    const float* Wh = (const float*)d_in[4];
    const float* Ur = (const float*)d_in[5];
    const float* Uz = (const float*)d_in[6];
    const float* Uh = (const float*)d_in[7];
    const float* br = (const float*)d_in[8];
    const float* bz = (const float*)d_in[9];
    const float* bh = (const float*)d_in[10];
    float* out = (float*)d_out;

    // smem: 2 asm arrays (8*264 floats = 8448B each) + 2 reduce arrays (16KB each)
    constexpr int SMEM_SCAN = 2 * (GR * AST * 4) + 2 * 16384;   // 49664 B
    cudaFuncSetAttribute(scan_kernel, cudaFuncAttributeMaxDynamicSharedMemorySize, SMEM_SCAN);

    proj_kernel<<<dim3(MTOT / 128, H_ / 64, 3), 256>>>(x, Wz, Wr, Wh, bz, br, bh);
    reset_kernel<<<256, 256>>>();
    scan_kernel<<<NG * NC, 256, SMEM_SCAN>>>(Uz, Ur, Uh, hdecay, out);
}

// round 14
// speedup vs baseline: 1.2624x; 1.2624x over previous
#include <cuda_runtime.h>
#include <cstdint>

// Problem constants
constexpr int B_  = 256;
constexpr int T_  = 512;
constexpr int H_  = 256;

// Scan decomposition: 16 batch groups x 8 column CTAs (champion R7 skeleton)
constexpr int NC  = 8;
constexpr int HC  = 32;
constexpr int NBG = 16;
constexpr int NB  = 16;
constexpr int AST = 384;   // asm_h row stride: [0:256)=h / rh-x shared, [256:384)=x_t

// ---------------- device scratch ----------------
__device__ float g_h [2][NBG][NB][H_];         // pre-decayed h, double-buffered
__device__ float g_rh[2][NBG][NB][H_];         // r*h_dec, double-buffered
__device__ unsigned g_cnt_rh[NBG][NC][32];     // per-producer flags (128B padded)
__device__ unsigned g_cnt_h [NBG][NC][32];

// ---------------- f32x2 helpers ----------------
__device__ __forceinline__ unsigned long long pack2(float a, float b) {
    unsigned long long r;
    asm("mov.b64 %0, {%1,%2};" : "=l"(r) : "f"(a), "f"(b));
    return r;
}
__device__ __forceinline__ void fma2(unsigned long long& d, unsigned long long a, unsigned long long b) {
    asm("fma.rn.f32x2 %0, %1, %2, %0;" : "+l"(d) : "l"(a), "l"(b));
}
__device__ __forceinline__ unsigned long long add2(unsigned long long a, unsigned long long b) {
    unsigned long long r;
    asm("add.rn.f32x2 %0, %1, %2;" : "=l"(r) : "l"(a), "l"(b));
    return r;
}
__device__ __forceinline__ float fold2(unsigned long long v) {
    float lo, hi;
    asm("mov.b64 {%0,%1}, %2;" : "=f"(lo), "=f"(hi) : "l"(v));
    return lo + hi;
}

__device__ __forceinline__ float sigmoid_(float v) {
    float e = __expf(-v);
    return __fdividef(1.f, 1.f + e);
}
__device__ __forceinline__ float tanh_(float v) {
    float e = __expf(2.f * v);
    return __fdividef(e - 1.f, e + 1.f);
}

// ---------------- flag primitives (champion: tid0 release-store value) -------
__device__ __forceinline__ void set_flag(unsigned* f, unsigned v) {
    asm volatile("st.release.gpu.global.u32 [%0], %1;" :: "l"(f), "r"(v) : "memory");
}
__device__ __forceinline__ void poll_ge(const unsigned* f, unsigned need) {
    unsigned v;
    do {
        asm volatile("ld.acquire.gpu.global.u32 %0, [%1];" : "=r"(v) : "l"(f) : "memory");
    } while (v < need);
}

// ================= reset: zero flags + g_h buffer 0 =================
__global__ void reset_kernel() {
    int i = blockIdx.x * 256 + threadIdx.x;
    if (i < NBG * NB * H_) ((float*)g_h)[i] = 0.f;
    if (i < NBG * NC * 32) {
        ((unsigned*)g_cnt_rh)[i] = 0;
        ((unsigned*)g_cnt_h)[i]  = 0;
    }
}

// ================= fused persistent scan (champion skeleton, augmented K) ====
// pre-activation = [h_dec | x_t] @ [U ; W] + b for each gate.
// Warp w: h k-slice [32w,32w+32), x k-slice [16w,16w+16); gather source CTA w.
// Thread (w,l) finalizes rows {w, w+8} at column j.
__global__ __launch_bounds__(256, 1) void scan_kernel(
    const float* __restrict__ x,
    const float* __restrict__ Uz, const float* __restrict__ Ur, const float* __restrict__ Uh,
    const float* __restrict__ Wz, const float* __restrict__ Wr, const float* __restrict__ Wh,
    const float* __restrict__ bz, const float* __restrict__ br, const float* __restrict__ bh,
    const float* __restrict__ hdecay, float* __restrict__ out)
{
    extern __shared__ float sm[];
    float* asm_h  = sm;                                                // [16][384] 24KB
    float* asm_rh = sm + NB * AST;                                     // [16][256] 16KB
    unsigned long long* red_z = (unsigned long long*)(asm_rh + NB * 256); // [8][16][32] 32KB
    unsigned long long* red_r = red_z + 4096;                             // 32KB

    const int tid = threadIdx.x;
    const int w = tid >> 5;          // warp id: k-slices + gather source CTA w
    const int l = tid & 31;
    const int grp = blockIdx.x >> 3;
    const int cg  = blockIdx.x & 7;
    const int j = cg * HC + l;
    const int b0g = grp * NB;

    // --- weights: h-part (32 k per warp) + x-part (16 k per warp), f32x2 ---
    unsigned long long uz2[16], ur2[16], uh2[16];
    #pragma unroll
    for (int p = 0; p < 16; ++p) {
        int k = w * 32 + 2 * p;
        uz2[p] = pack2(Uz[(size_t)k * H_ + j], Uz[(size_t)(k + 1) * H_ + j]);
        ur2[p] = pack2(Ur[(size_t)k * H_ + j], Ur[(size_t)(k + 1) * H_ + j]);
        uh2[p] = pack2(Uh[(size_t)k * H_ + j], Uh[(size_t)(k + 1) * H_ + j]);
    }
    unsigned long long wz2[8], wr2[8], wh2[8];
    #pragma unroll
    for (int p = 0; p < 8; ++p) {
        int k = w * 16 + 2 * p;
        wz2[p] = pack2(Wz[(size_t)k * H_ + j], Wz[(size_t)(k + 1) * H_ + j]);
        wr2[p] = pack2(Wr[(size_t)k * H_ + j], Wr[(size_t)(k + 1) * H_ + j]);
        wh2[p] = pack2(Wh[(size_t)k * H_ + j], Wh[(size_t)(k + 1) * H_ + j]);
    }
    const float bzv = bz[j], brv = br[j], bhv = bh[j];

    const unsigned* frh = &g_cnt_rh[grp][w][0];   // source CTA w's flags
    const unsigned* fh  = &g_cnt_h [grp][w][0];
    unsigned* myfrh = &g_cnt_rh[grp][cg][0];      // own flags
    unsigned* myfh  = &g_cnt_h [grp][cg][0];

    // gather mapping: lane l -> row l>>1, float4 block (l&1)*4 .. +3
    const int gr = l >> 1;
    const int gh = (l & 1) * 4;

    // x staging mapping: thread -> (row tid>>4, 8 floats at seg*8)
    const int xrw = tid >> 4;
    const int xsg = tid & 15;

    // --- init: h_dec(t=0) = 0; stage x(0) ---
    #pragma unroll
    for (int i = 0; i < 16; ++i) asm_h[xrw * AST + xsg * 16 + i] = 0.f;
    {
        const float4* xs = (const float4*)&x[((size_t)(b0g + xrw) * T_ + 0) * 128 + xsg * 8];
        float4 a = xs[0], b4 = xs[1];
        *(float4*)&asm_h[xrw * AST + 256 + xsg * 8]     = a;
        *(float4*)&asm_h[xrw * AST + 256 + xsg * 8 + 4] = b4;
    }
    __syncthreads();

    for (int t = 0; t < T_; ++t) {
        const int p = t & 1;
        const size_t m0 = (size_t)(b0g + w) * T_ + t;
        const size_t m1 = (size_t)(b0g + w + 8) * T_ + t;
        const bool more = (t + 1 < T_);

        float decn0 = 0.f, decn1 = 0.f;
        if (more) { decn0 = hdecay[m0 + 1]; decn1 = hdecay[m1 + 1]; }

        // ---- A: wait for source CTA w's h(t), gather slice into smem ----
        poll_ge(fh, (unsigned)t);
        {
            const float4* src = (const float4*)&g_h[p][grp][gr][w * 32 + gh * 4];
            float4 v0 = __ldcg(src + 0), v1 = __ldcg(src + 1);
            float4 v2 = __ldcg(src + 2), v3 = __ldcg(src + 3);
            float4* dst = (float4*)&asm_h[gr * AST + w * 32 + gh * 4];
            dst[0] = v0; dst[1] = v1; dst[2] = v2; dst[3] = v3;
        }
        __syncwarp();

        // ---- B: merged z+r augmented GEMM (h part + x part) ----
        #pragma unroll 1
        for (int b = 0; b < NB; ++b) {
            unsigned long long az0 = 0, az1 = 0, ar0 = 0, ar1 = 0;
            const float* hrow = &asm_h[b * AST + w * 32];
            #pragma unroll
            for (int q = 0; q < 8; ++q) {
                ulonglong2 hv = *(const ulonglong2*)(hrow + q * 4);
                fma2(az0, hv.x, uz2[2 * q]);
                fma2(az1, hv.y, uz2[2 * q + 1]);
                fma2(ar0, hv.x, ur2[2 * q]);
                fma2(ar1, hv.y, ur2[2 * q + 1]);
            }
            const float* xrow = &asm_h[b * AST + 256 + w * 16];
            #pragma unroll
            for (int q = 0; q < 4; ++q) {
                ulonglong2 xv = *(const ulonglong2*)(xrow + q * 4);
                fma2(az0, xv.x, wz2[2 * q]);
                fma2(az1, xv.y, wz2[2 * q + 1]);
                fma2(ar0, xv.x, wr2[2 * q]);
                fma2(ar1, xv.y, wr2[2 * q + 1]);
            }
            red_z[(w * 16 + b) * 32 + l] = add2(az0, az1);
            red_r[(w * 16 + b) * 32 + l] = add2(ar0, ar1);
        }
        __syncthreads();   // S1

        // ---- C: r reduce + publish rh rows {w, w+8} ----
        float hd0, hd1;
        {
            unsigned long long s0 = 0, s1 = 0;
            #pragma unroll
            for (int ww = 0; ww < 8; ++ww) {
                s0 = add2(s0, red_r[(ww * 16 + w) * 32 + l]);
                s1 = add2(s1, red_r[(ww * 16 + w + 8) * 32 + l]);
            }
            float r0 = sigmoid_(fold2(s0) + brv);
            float r1 = sigmoid_(fold2(s1) + brv);
            hd0 = asm_h[w * AST + j];
            hd1 = asm_h[(w + 8) * AST + j];
            __stcg(&g_rh[p][grp][w][j],     r0 * hd0);
            __stcg(&g_rh[p][grp][w + 8][j], r1 * hd1);
        }
        __syncthreads();   // S2: all rh stores issued before release
        if (tid == 0) set_flag(myfrh, (unsigned)(t + 1));

        // ---- D: z reduce (fills rh propagation latency) ----
        float zv0, zv1;
        {
            unsigned long long s0 = 0, s1 = 0;
            #pragma unroll
            for (int ww = 0; ww < 8; ++ww) {
                s0 = add2(s0, red_z[(ww * 16 + w) * 32 + l]);
                s1 = add2(s1, red_z[(ww * 16 + w + 8) * 32 + l]);
            }
            zv0 = sigmoid_(fold2(s0) + bzv);
            zv1 = sigmoid_(fold2(s1) + bzv);
        }

        // ---- E: wait for source CTA w's rh, gather slice ----
        poll_ge(frh, (unsigned)(t + 1));
        {
            const float4* src = (const float4*)&g_rh[p][grp][gr][w * 32 + gh * 4];
            float4 v0 = __ldcg(src + 0), v1 = __ldcg(src + 1);
            float4 v2 = __ldcg(src + 2), v3 = __ldcg(src + 3);
            float4* dst = (float4*)&asm_rh[gr * 256 + w * 32 + gh * 4];
            dst[0] = v0; dst[1] = v1; dst[2] = v2; dst[3] = v3;
        }
        __syncwarp();

        // ---- F: h augmented GEMM (rh part from asm_rh, x part from asm_h) ----
        #pragma unroll 1
        for (int b = 0; b < NB; ++b) {
            unsigned long long ah0 = 0, ah1 = 0;
            const float* hrow = &asm_rh[b * 256 + w * 32];
            #pragma unroll
            for (int q = 0; q < 8; ++q) {
                ulonglong2 hv = *(const ulonglong2*)(hrow + q * 4);
                fma2(ah0, hv.x, uh2[2 * q]);
                fma2(ah1, hv.y, uh2[2 * q + 1]);
            }
            const float* xrow = &asm_h[b * AST + 256 + w * 16];
            #pragma unroll
            for (int q = 0; q < 4; ++q) {
                ulonglong2 xv = *(const ulonglong2*)(xrow + q * 4);
                fma2(ah0, xv.x, wh2[2 * q]);
                fma2(ah1, xv.y, wh2[2 * q + 1]);
            }
            red_r[(w * 16 + b) * 32 + l] = add2(ah0, ah1);
        }
        __syncthreads();   // S3: F done (incl. all reads of x(t))

        // ---- H: h reduce, combine, publish pre-decayed h; stage x(t+1) ----
        float h0, h1;
        {
            unsigned long long s0 = 0, s1 = 0;
            #pragma unroll
            for (int ww = 0; ww < 8; ++ww) {
                s0 = add2(s0, red_r[(ww * 16 + w) * 32 + l]);
                s1 = add2(s1, red_r[(ww * 16 + w + 8) * 32 + l]);
            }
            float hp0 = tanh_(fold2(s0) + bhv);
            float hp1 = tanh_(fold2(s1) + bhv);
            h0 = (1.f - zv0) * hd0 + zv0 * hp0;
            h1 = (1.f - zv1) * hd1 + zv1 * hp1;
            if (more) {
                __stcg(&g_h[(t + 1) & 1][grp][w][j],     h0 * decn0);
                __stcg(&g_h[(t + 1) & 1][grp][w + 8][j], h1 * decn1);
            }
        }
        if (more) {   // stage x(t+1) into asm_h x-region (ordered by S4 for next B)
            const float4* xs = (const float4*)&x[((size_t)(b0g + xrw) * T_ + (t + 1)) * 128 + xsg * 8];
            float4 a = xs[0], b4 = xs[1];
            *(float4*)&asm_h[xrw * AST + 256 + xsg * 8]     = a;
            *(float4*)&asm_h[xrw * AST + 256 + xsg * 8 + 4] = b4;
        }
        __syncthreads();   // S4: h stores + x staging ordered before release/next step
        if (more && tid == 0) set_flag(myfh, (unsigned)(t + 1));

        // ---- I: outputs (off critical path) ----
        out[m0 * 256 + j] = h0;
        out[m1 * 256 + j] = h1;
    }
}

// ================= launch =================
extern "C" void kernel_launch(void* const* d_in, const int* /*in_sizes*/, int /*n_in*/,
                              void* d_out, int /*out_size*/)
{
    const float* x      = (const float*)d_in[0];
    const float* hdecay = (const float*)d_in[1];
    const float* Wr = (const float*)d_in[2];
    const float* Wz = (const float*)d_in[3];
    const float* Wh = (const float*)d_in[4];
    const float* Ur = (const float*)d_in[5];
    const float* Uz = (const float*)d_in[6];
    const float* Uh = (const float*)d_in[7];
    const float* br = (const float*)d_in[8];
    const float* bz = (const float*)d_in[9];
    const float* bh = (const float*)d_in[10];
    float* out = (float*)d_out;

    // smem: asm_h 16*384*4 + asm_rh 16*256*4 + red_z/red_r 32KB each
    constexpr int SMEM_SCAN = NB * AST * 4 + NB * 256 * 4 + 2 * 32768;   // 106496 B
    cudaFuncSetAttribute(scan_kernel, cudaFuncAttributeMaxDynamicSharedMemorySize, SMEM_SCAN);

    reset_kernel<<<256, 256>>>();
    scan_kernel<<<NBG * NC, 256, SMEM_SCAN>>>(
        x, Uz, Ur, Uh, Wz, Wr, Wh, bz, br, bh, hdecay, out);
}

// round 16
// speedup vs baseline: 1.4960x; 1.1850x over previous
#include <cuda_runtime.h>
#include <cstdint>

// Problem constants
constexpr int B_  = 256;
constexpr int T_  = 512;
constexpr int H_  = 256;
constexpr int MTOT = B_ * T_;
constexpr size_t MH = (size_t)MTOT * H_;

// Scan decomposition: 16 batch groups x 8 column CTAs (champion skeleton)
constexpr int NC  = 8;
constexpr int HC  = 32;
constexpr int NBG = 16;
constexpr int NB  = 16;
constexpr int AST = 264;   // smem row stride (floats)

// ---------------- device scratch ----------------
__device__ float g_xp[3 * MH];                        // projected inputs [gate][m][H]
__device__ unsigned long long g_h64 [2][NBG][NB][H_]; // (tag,val) pre-decayed h, 2-buf
__device__ unsigned long long g_rh64[2][NBG][NB][H_]; // (tag,val) r*h_dec, 2-buf
constexpr int TAGWORDS = 2 * NBG * NB * H_;           // 131072 words per array

// ---------------- f32x2 helpers ----------------
__device__ __forceinline__ unsigned long long pack2(float a, float b) {
    unsigned long long r;
    asm("mov.b64 %0, {%1,%2};" : "=l"(r) : "f"(a), "f"(b));
    return r;
}
__device__ __forceinline__ void fma2(unsigned long long& d, unsigned long long a, unsigned long long b) {
    asm("fma.rn.f32x2 %0, %1, %2, %0;" : "+l"(d) : "l"(a), "l"(b));
}
__device__ __forceinline__ unsigned long long add2(unsigned long long a, unsigned long long b) {
    unsigned long long r;
    asm("add.rn.f32x2 %0, %1, %2;" : "=l"(r) : "l"(a), "l"(b));
    return r;
}
__device__ __forceinline__ float fold2(unsigned long long v) {
    float lo, hi;
    asm("mov.b64 {%0,%1}, %2;" : "=f"(lo), "=f"(hi) : "l"(v));
    return lo + hi;
}

__device__ __forceinline__ float sigmoid_(float v) {
    float e = __expf(-v);
    return __fdividef(1.f, 1.f + e);
}
__device__ __forceinline__ float tanh_(float v) {
    float e = __expf(2.f * v);
    return __fdividef(e - 1.f, e + 1.f);
}

// ---------------- tagged-word exchange primitives (morally strong b64) -------
__device__ __forceinline__ unsigned long long tagpack(float v, unsigned tag) {
    return ((unsigned long long)tag << 32) | (unsigned long long)__float_as_uint(v);
}
__device__ __forceinline__ void st_tag(unsigned long long* p, unsigned long long v) {
    asm volatile("st.relaxed.gpu.global.b64 [%0], %1;" :: "l"(p), "l"(v) : "memory");
}
// Spin-gather 16 tagged rows of one column; commit values into smem column.
__device__ __forceinline__ void gather16(const unsigned long long* base, unsigned want,
                                         float* smem_col /* stride AST */) {
    unsigned long long v[16];
    bool ok;
    do {
        #pragma unroll
        for (int b = 0; b < 16; ++b)
            asm volatile("ld.relaxed.gpu.global.b64 %0, [%1];"
                         : "=l"(v[b]) : "l"(base + (size_t)b * H_) : "memory");
        ok = true;
        #pragma unroll
        for (int b = 0; b < 16; ++b)
            ok &= ((unsigned)(v[b] >> 32) == want);
    } while (!ok);
    #pragma unroll
    for (int b = 0; b < 16; ++b)
        smem_col[b * AST] = __uint_as_float((unsigned)v[b]);
}

// ================= projection GEMM (proven, ~571us) =================
__global__ __launch_bounds__(256) void proj_kernel(
    const float* __restrict__ x,
    const float* __restrict__ Wz, const float* __restrict__ Wr, const float* __restrict__ Wh,
    const float* __restrict__ bz, const float* __restrict__ br, const float* __restrict__ bh)
{
    __shared__ float As[32 * 132];
    __shared__ float Bs[32 * 64];

    const int g = blockIdx.z;
    const float* W    = (g == 0) ? Wz : (g == 1) ? Wr : Wh;
    const float* bias = (g == 0) ? bz : (g == 1) ? br : bh;
    float* out = g_xp + (size_t)g * MH;

    const int mtile = blockIdx.x * 128;
    const int ntile = blockIdx.y * 64;
    const int tid = threadIdx.x;
    const int tm = tid >> 4;
    const int tn = tid & 15;

    float acc[8][4] = {};

    for (int kc = 0; kc < 128; kc += 32) {
        __syncthreads();
        #pragma unroll
        for (int it = 0; it < 4; ++it) {
            int idx = tid + it * 256;
            int m = idx >> 3, c4 = idx & 7;
            float4 v = *(const float4*)&x[(size_t)(mtile + m) * 128 + kc + c4 * 4];
            As[(c4 * 4 + 0) * 132 + m] = v.x;
            As[(c4 * 4 + 1) * 132 + m] = v.y;
            As[(c4 * 4 + 2) * 132 + m] = v.z;
            As[(c4 * 4 + 3) * 132 + m] = v.w;
        }
        #pragma unroll
        for (int it = 0; it < 2; ++it) {
            int idx = tid + it * 256;
            int kk = idx >> 4, n4 = idx & 15;
            float4 v = *(const float4*)&W[(size_t)(kc + kk) * 256 + ntile + n4 * 4];
            *(float4*)&Bs[kk * 64 + n4 * 4] = v;
        }
        __syncthreads();

        #pragma unroll
        for (int kk = 0; kk < 32; ++kk) {
            float4 a0 = *(const float4*)&As[kk * 132 + tm * 8];
            float4 a1 = *(const float4*)&As[kk * 132 + tm * 8 + 4];
            float4 bv = *(const float4*)&Bs[kk * 64 + tn * 4];
            float a[8] = {a0.x, a0.y, a0.z, a0.w, a1.x, a1.y, a1.z, a1.w};
            #pragma unroll
            for (int i = 0; i < 8; i++) {
                acc[i][0] += a[i] * bv.x;
                acc[i][1] += a[i] * bv.y;
                acc[i][2] += a[i] * bv.z;
                acc[i][3] += a[i] * bv.w;
            }
        }
    }

    float4 bb = *(const float4*)&bias[ntile + tn * 4];
    #pragma unroll
    for (int i = 0; i < 8; i++) {
        float4 o = make_float4(acc[i][0] + bb.x, acc[i][1] + bb.y,
                               acc[i][2] + bb.z, acc[i][3] + bb.w);
        *(float4*)&out[(size_t)(mtile + tm * 8 + i) * 256 + ntile + tn * 4] = o;
    }
}

// ====== reset: zero ALL tagged words (both parities, both arrays) each run ====
// Tags repeat across graph replays; stale words from the previous replay would
// satisfy this run's polls. Full zeroing makes every tag>=1 wait correctly and
// makes g_h64[0] (tag 0, value 0) the valid t=0 state.
__global__ void reset_kernel() {
    int i = blockIdx.x * 256 + threadIdx.x;
    if (i < TAGWORDS) {
        ((unsigned long long*)g_h64)[i]  = 0ull;
        ((unsigned long long*)g_rh64)[i] = 0ull;
    }
}

// ================= persistent recurrent scan (tagged exchange) =================
// Champion phase order; flags fused into data words; 2 barriers/step.
__global__ __launch_bounds__(256, 1) void scan_kernel(
    const float* __restrict__ Uz, const float* __restrict__ Ur, const float* __restrict__ Uh,
    const float* __restrict__ hdecay, float* __restrict__ out)
{
    extern __shared__ float sm[];
    float* asm_h  = sm;                                              // [16][264] 16.5KB
    float* asm_rh = sm + NB * AST;                                   // [16][264] 16.5KB
    unsigned long long* red_z = (unsigned long long*)(sm + 2 * NB * AST); // [8][16][32] 32KB
    unsigned long long* red_r = red_z + 4096;                             // 32KB
    unsigned long long* red_h = red_z + 8192;                             // 32KB

    const int tid = threadIdx.x;
    const int w = tid >> 5;          // warp -> k block [32w,32w+32), gather source CTA w
    const int l = tid & 31;
    const int grp = blockIdx.x >> 3;
    const int cg  = blockIdx.x & 7;
    const int j = cg * HC + l;       // column this thread finalizes
    const int gcol = w * 32 + l;     // column this thread gathers (source stripe)
    const int b0g = grp * NB;

    // weights: packed f32x2 over k-pairs
    unsigned long long uz2[16], ur2[16], uh2[16];
    #pragma unroll
    for (int p = 0; p < 16; ++p) {
        int k = w * 32 + 2 * p;
        uz2[p] = pack2(Uz[(size_t)k * H_ + j], Uz[(size_t)(k + 1) * H_ + j]);
        ur2[p] = pack2(Ur[(size_t)k * H_ + j], Ur[(size_t)(k + 1) * H_ + j]);
        uh2[p] = pack2(Uh[(size_t)k * H_ + j], Uh[(size_t)(k + 1) * H_ + j]);
    }

    // x projections for t=0
    size_t mb0 = (size_t)(b0g + w) * T_;
    size_t mb1 = (size_t)(b0g + w + 8) * T_;
    float xz0 = g_xp[mb0 * 256 + j],          xz1 = g_xp[mb1 * 256 + j];
    float xr0 = g_xp[MH + mb0 * 256 + j],     xr1 = g_xp[MH + mb1 * 256 + j];
    float xh0 = g_xp[2 * MH + mb0 * 256 + j], xh1 = g_xp[2 * MH + mb1 * 256 + j];

    for (int t = 0; t < T_; ++t) {
        const int p = t & 1;
        const size_t m0 = (size_t)(b0g + w) * T_ + t;
        const size_t m1 = (size_t)(b0g + w + 8) * T_ + t;
        const bool more = (t + 1 < T_);

        float decn0 = 0.f, decn1 = 0.f;
        if (more) { decn0 = hdecay[m0 + 1]; decn1 = hdecay[m1 + 1]; }

        // ---- A: tagged spin-gather of h(t) slice (tag == t) ----
        gather16(&g_h64[p][grp][0][gcol], (unsigned)t, &asm_h[gcol]);
        __syncwarp();

        // ---- B: merged z+r GEMM (one pass over own stripe) ----
        #pragma unroll 1
        for (int b = 0; b < NB; ++b) {
            unsigned long long az0 = 0, az1 = 0, ar0 = 0, ar1 = 0;
            const float* hrow = &asm_h[b * AST + w * 32];
            #pragma unroll
            for (int q = 0; q < 8; ++q) {
                ulonglong2 hv = *(const ulonglong2*)(hrow + q * 4);
                fma2(az0, hv.x, uz2[2 * q]);
                fma2(az1, hv.y, uz2[2 * q + 1]);
                fma2(ar0, hv.x, ur2[2 * q]);
                fma2(ar1, hv.y, ur2[2 * q + 1]);
            }
            red_z[(w * 16 + b) * 32 + l] = add2(az0, az1);
            red_r[(w * 16 + b) * 32 + l] = add2(ar0, ar1);
        }
        __syncthreads();   // S1: partials + all h staging visible CTA-wide

        // ---- C: r reduce, publish tagged rh rows {w, w+8} immediately ----
        float hd0, hd1;
        {
            unsigned long long s0 = 0, s1 = 0;
            #pragma unroll
            for (int ww = 0; ww < 8; ++ww) {
                s0 = add2(s0, red_r[(ww * 16 + w) * 32 + l]);
                s1 = add2(s1, red_r[(ww * 16 + w + 8) * 32 + l]);
            }
            float r0 = sigmoid_(fold2(s0) + xr0);
            float r1 = sigmoid_(fold2(s1) + xr1);
            hd0 = asm_h[w * AST + j];
            hd1 = asm_h[(w + 8) * AST + j];
            st_tag(&g_rh64[p][grp][w][j],     tagpack(r0 * hd0, (unsigned)(t + 1)));
            st_tag(&g_rh64[p][grp][w + 8][j], tagpack(r1 * hd1, (unsigned)(t + 1)));
        }

        // ---- D: z reduce (fills rh propagation latency) ----
        float zv0, zv1;
        {
            unsigned long long s0 = 0, s1 = 0;
            #pragma unroll
            for (int ww = 0; ww < 8; ++ww) {
                s0 = add2(s0, red_z[(ww * 16 + w) * 32 + l]);
                s1 = add2(s1, red_z[(ww * 16 + w + 8) * 32 + l]);
            }
            zv0 = sigmoid_(fold2(s0) + xz0);
            zv1 = sigmoid_(fold2(s1) + xz1);
        }

        // ---- E: tagged spin-gather of rh(t) slice (tag == t+1) ----
        gather16(&g_rh64[p][grp][0][gcol], (unsigned)(t + 1), &asm_rh[gcol]);
        __syncwarp();

        // ---- F: h GEMM (partials into red_h; no hazard with C/D) ----
        #pragma unroll 1
        for (int b = 0; b < NB; ++b) {
            unsigned long long ah0 = 0, ah1 = 0;
            const float* hrow = &asm_rh[b * AST + w * 32];
            #pragma unroll
            for (int q = 0; q < 8; ++q) {
                ulonglong2 hv = *(const ulonglong2*)(hrow + q * 4);
                fma2(ah0, hv.x, uh2[2 * q]);
                fma2(ah1, hv.y, uh2[2 * q + 1]);
            }
            red_h[(w * 16 + b) * 32 + l] = add2(ah0, ah1);
        }
        __syncthreads();   // S3

        // ---- H: h reduce, combine, publish tagged pre-decayed h(t+1) ----
        float h0, h1;
        {
            unsigned long long s0 = 0, s1 = 0;
            #pragma unroll
            for (int ww = 0; ww < 8; ++ww) {
                s0 = add2(s0, red_h[(ww * 16 + w) * 32 + l]);
                s1 = add2(s1, red_h[(ww * 16 + w + 8) * 32 + l]);
            }
            float hp0 = tanh_(fold2(s0) + xh0);
            float hp1 = tanh_(fold2(s1) + xh1);
            h0 = (1.f - zv0) * hd0 + zv0 * hp0;
            h1 = (1.f - zv1) * hd1 + zv1 * hp1;
            if (more) {
                st_tag(&g_h64[(t + 1) & 1][grp][w][j],
                       tagpack(h0 * decn0, (unsigned)(t + 1)));
                st_tag(&g_h64[(t + 1) & 1][grp][w + 8][j],
                       tagpack(h1 * decn1, (unsigned)(t + 1)));
            }
        }

        // ---- I: outputs + next-step x prefetch (off critical path) ----
        out[m0 * 256 + j] = h0;
        out[m1 * 256 + j] = h1;
        if (more) {
            xz0 = g_xp[(m0 + 1) * 256 + j];          xz1 = g_xp[(m1 + 1) * 256 + j];
            xr0 = g_xp[MH + (m0 + 1) * 256 + j];     xr1 = g_xp[MH + (m1 + 1) * 256 + j];
            xh0 = g_xp[2 * MH + (m0 + 1) * 256 + j]; xh1 = g_xp[2 * MH + (m1 + 1) * 256 + j];
        }
    }
}

// ================= launch =================
extern "C" void kernel_launch(void* const* d_in, const int* /*in_sizes*/, int /*n_in*/,
                              void* d_out, int /*out_size*/)
{
    const float* x      = (const float*)d_in[0];
    const float* hdecay = (const float*)d_in[1];
    const float* Wr = (const float*)d_in[2];
    const float* Wz = (const float*)d_in[3];
    const float* Wh = (const float*)d_in[4];
    const float* Ur = (const float*)d_in[5];
    const float* Uz = (const float*)d_in[6];
    const float* Uh = (const float*)d_in[7];
    const float* br = (const float*)d_in[8];
    const float* bz = (const float*)d_in[9];
    const float* bh = (const float*)d_in[10];
    float* out = (float*)d_out;

    // smem: 2 asm arrays (16*264 floats = 16896B each) + 3 reduce arrays (32KB each)
    constexpr int SMEM_SCAN = 2 * (NB * AST * 4) + 3 * 32768;   // 131840 B
    cudaFuncSetAttribute(scan_kernel, cudaFuncAttributeMaxDynamicSharedMemorySize, SMEM_SCAN);

    proj_kernel<<<dim3(MTOT / 128, H_ / 64, 3), 256>>>(x, Wz, Wr, Wh, bz, br, bh);
    reset_kernel<<<(TAGWORDS + 255) / 256, 256>>>();
    scan_kernel<<<NBG * NC, 256, SMEM_SCAN>>>(Uz, Ur, Uh, hdecay, out);
}

// round 17
// speedup vs baseline: 1.5432x; 1.0316x over previous
#include <cuda_runtime.h>
#include <cstdint>

// Problem constants
constexpr int B_  = 256;
constexpr int T_  = 512;
constexpr int H_  = 256;
constexpr int MTOT = B_ * T_;
constexpr size_t MH = (size_t)MTOT * H_;

// Scan decomposition: 16 batch groups x 8 column CTAs (champion skeleton)
constexpr int NC  = 8;
constexpr int HC  = 32;
constexpr int NBG = 16;
constexpr int NB  = 16;
constexpr int AST = 264;   // smem row stride (floats)

// ---------------- device scratch ----------------
__device__ float g_xp[3 * MH];                        // projected inputs [gate][m][H]
__device__ unsigned long long g_h64 [2][NBG][NB][H_]; // (tag,val) pre-decayed h, 2-buf
__device__ unsigned long long g_rh64[2][NBG][NB][H_]; // (tag,val) r*h_dec, 2-buf
constexpr int TAGWORDS = 2 * NBG * NB * H_;           // 131072 words per array

// ---------------- f32x2 helpers ----------------
__device__ __forceinline__ unsigned long long pack2(float a, float b) {
    unsigned long long r;
    asm("mov.b64 %0, {%1,%2};" : "=l"(r) : "f"(a), "f"(b));
    return r;
}
__device__ __forceinline__ void fma2(unsigned long long& d, unsigned long long a, unsigned long long b) {
    asm("fma.rn.f32x2 %0, %1, %2, %0;" : "+l"(d) : "l"(a), "l"(b));
}
__device__ __forceinline__ unsigned long long add2(unsigned long long a, unsigned long long b) {
    unsigned long long r;
    asm("add.rn.f32x2 %0, %1, %2;" : "=l"(r) : "l"(a), "l"(b));
    return r;
}
__device__ __forceinline__ float fold2(unsigned long long v) {
    float lo, hi;
    asm("mov.b64 {%0,%1}, %2;" : "=f"(lo), "=f"(hi) : "l"(v));
    return lo + hi;
}

__device__ __forceinline__ float sigmoid_(float v) {
    float e = __expf(-v);
    return __fdividef(1.f, 1.f + e);
}
__device__ __forceinline__ float tanh_(float v) {
    float e = __expf(2.f * v);
    return __fdividef(e - 1.f, e + 1.f);
}

// ---------------- tagged-word exchange primitives (morally strong b64) -------
__device__ __forceinline__ unsigned long long tagpack(float v, unsigned tag) {
    return ((unsigned long long)tag << 32) | (unsigned long long)__float_as_uint(v);
}
__device__ __forceinline__ void st_tag(unsigned long long* p, unsigned long long v) {
    asm volatile("st.relaxed.gpu.global.b64 [%0], %1;" :: "l"(p), "l"(v) : "memory");
}
// Spin-gather 16 tagged rows of one column; commit values into smem column.
__device__ __forceinline__ void gather16(const unsigned long long* base, unsigned want,
                                         float* smem_col /* stride AST */) {
    unsigned long long v[16];
    bool ok;
    do {
        #pragma unroll
        for (int b = 0; b < 16; ++b)
            asm volatile("ld.relaxed.gpu.global.b64 %0, [%1];"
                         : "=l"(v[b]) : "l"(base + (size_t)b * H_) : "memory");
        ok = true;
        #pragma unroll
        for (int b = 0; b < 16; ++b)
            ok &= ((unsigned)(v[b] >> 32) == want);
    } while (!ok);
    #pragma unroll
    for (int b = 0; b < 16; ++b)
        smem_col[b * AST] = __uint_as_float((unsigned)v[b]);
}

// ================= projection GEMM v2: 128M x 128N tile, 8x8 per thread ======
// 64 FMA per 4 LDS.128 in the inner loop (was 32 per 3) -> ~94% fma issue ratio.
__global__ __launch_bounds__(256) void proj_kernel(
    const float* __restrict__ x,
    const float* __restrict__ Wz, const float* __restrict__ Wr, const float* __restrict__ Wh,
    const float* __restrict__ bz, const float* __restrict__ br, const float* __restrict__ bh)
{
    __shared__ float As[32 * 132];   // [k][m] transposed, pad 132 (16.9KB)
    __shared__ float Bs[32 * 128];   // [k][n]                    (16KB)

    const int g = blockIdx.z;
    const float* W    = (g == 0) ? Wz : (g == 1) ? Wr : Wh;
    const float* bias = (g == 0) ? bz : (g == 1) ? br : bh;
    float* out = g_xp + (size_t)g * MH;

    const int mtile = blockIdx.x * 128;
    const int ntile = blockIdx.y * 128;
    const int tid = threadIdx.x;
    const int tm = tid >> 4;      // 0..15 -> 8 m-rows each
    const int tn = tid & 15;      // 0..15 -> 8 n-cols each

    float acc[8][8] = {};

    for (int kc = 0; kc < 128; kc += 32) {
        __syncthreads();
        // stage A chunk [128m x 32k] -> As[k][m]
        #pragma unroll
        for (int it = 0; it < 4; ++it) {
            int idx = tid + it * 256;          // float4 index 0..1023
            int m = idx >> 3, c4 = idx & 7;
            float4 v = *(const float4*)&x[(size_t)(mtile + m) * 128 + kc + c4 * 4];
            As[(c4 * 4 + 0) * 132 + m] = v.x;
            As[(c4 * 4 + 1) * 132 + m] = v.y;
            As[(c4 * 4 + 2) * 132 + m] = v.z;
            As[(c4 * 4 + 3) * 132 + m] = v.w;
        }
        // stage B chunk [32k x 128n]
        #pragma unroll
        for (int it = 0; it < 4; ++it) {
            int idx = tid + it * 256;          // 0..1023
            int kk = idx >> 5, n4 = idx & 31;
            float4 v = *(const float4*)&W[(size_t)(kc + kk) * 256 + ntile + n4 * 4];
            *(float4*)&Bs[kk * 128 + n4 * 4] = v;
        }
        __syncthreads();

        #pragma unroll
        for (int kk = 0; kk < 32; ++kk) {
            float4 a0 = *(const float4*)&As[kk * 132 + tm * 8];
            float4 a1 = *(const float4*)&As[kk * 132 + tm * 8 + 4];
            float4 b0 = *(const float4*)&Bs[kk * 128 + tn * 8];
            float4 b1 = *(const float4*)&Bs[kk * 128 + tn * 8 + 4];
            float a[8] = {a0.x, a0.y, a0.z, a0.w, a1.x, a1.y, a1.z, a1.w};
            float b[8] = {b0.x, b0.y, b0.z, b0.w, b1.x, b1.y, b1.z, b1.w};
            #pragma unroll
            for (int i = 0; i < 8; i++) {
                #pragma unroll
                for (int n = 0; n < 8; n++) acc[i][n] += a[i] * b[n];
            }
        }
    }

    float4 bb0 = *(const float4*)&bias[ntile + tn * 8];
    float4 bb1 = *(const float4*)&bias[ntile + tn * 8 + 4];
    #pragma unroll
    for (int i = 0; i < 8; i++) {
        float4 o0 = make_float4(acc[i][0] + bb0.x, acc[i][1] + bb0.y,
                                acc[i][2] + bb0.z, acc[i][3] + bb0.w);
        float4 o1 = make_float4(acc[i][4] + bb1.x, acc[i][5] + bb1.y,
                                acc[i][6] + bb1.z, acc[i][7] + bb1.w);
        float* orow = &out[(size_t)(mtile + tm * 8 + i) * 256 + ntile + tn * 8];
        *(float4*)orow = o0;
        *(float4*)(orow + 4) = o1;
    }
}

// ====== reset: zero ALL tagged words (both parities, both arrays) each run ====
__global__ void reset_kernel() {
    int i = blockIdx.x * 256 + threadIdx.x;
    if (i < TAGWORDS) {
        ((unsigned long long*)g_h64)[i]  = 0ull;
        ((unsigned long long*)g_rh64)[i] = 0ull;
    }
}

// ================= persistent recurrent scan (tagged exchange — CHAMPION) ====
__global__ __launch_bounds__(256, 1) void scan_kernel(
    const float* __restrict__ Uz, const float* __restrict__ Ur, const float* __restrict__ Uh,
    const float* __restrict__ hdecay, float* __restrict__ out)
{
    extern __shared__ float sm[];
    float* asm_h  = sm;                                              // [16][264] 16.5KB
    float* asm_rh = sm + NB * AST;                                   // [16][264] 16.5KB
    unsigned long long* red_z = (unsigned long long*)(sm + 2 * NB * AST); // [8][16][32] 32KB
    unsigned long long* red_r = red_z + 4096;                             // 32KB
    unsigned long long* red_h = red_z + 8192;                             // 32KB

    const int tid = threadIdx.x;
    const int w = tid >> 5;          // warp -> k block [32w,32w+32), gather source CTA w
    const int l = tid & 31;
    const int grp = blockIdx.x >> 3;
    const int cg  = blockIdx.x & 7;
    const int j = cg * HC + l;       // column this thread finalizes
    const int gcol = w * 32 + l;     // column this thread gathers (source stripe)
    const int b0g = grp * NB;

    // weights: packed f32x2 over k-pairs
    unsigned long long uz2[16], ur2[16], uh2[16];
    #pragma unroll
    for (int p = 0; p < 16; ++p) {
        int k = w * 32 + 2 * p;
        uz2[p] = pack2(Uz[(size_t)k * H_ + j], Uz[(size_t)(k + 1) * H_ + j]);
        ur2[p] = pack2(Ur[(size_t)k * H_ + j], Ur[(size_t)(k + 1) * H_ + j]);
        uh2[p] = pack2(Uh[(size_t)k * H_ + j], Uh[(size_t)(k + 1) * H_ + j]);
    }

    // x projections for t=0
    size_t mb0 = (size_t)(b0g + w) * T_;
    size_t mb1 = (size_t)(b0g + w + 8) * T_;
    float xz0 = g_xp[mb0 * 256 + j],          xz1 = g_xp[mb1 * 256 + j];
    float xr0 = g_xp[MH + mb0 * 256 + j],     xr1 = g_xp[MH + mb1 * 256 + j];
    float xh0 = g_xp[2 * MH + mb0 * 256 + j], xh1 = g_xp[2 * MH + mb1 * 256 + j];

    for (int t = 0; t < T_; ++t) {
        const int p = t & 1;
        const size_t m0 = (size_t)(b0g + w) * T_ + t;
        const size_t m1 = (size_t)(b0g + w + 8) * T_ + t;
        const bool more = (t + 1 < T_);

        float decn0 = 0.f, decn1 = 0.f;
        if (more) { decn0 = hdecay[m0 + 1]; decn1 = hdecay[m1 + 1]; }

        // ---- A: tagged spin-gather of h(t) slice (tag == t) ----
        gather16(&g_h64[p][grp][0][gcol], (unsigned)t, &asm_h[gcol]);
        __syncwarp();

        // ---- B: merged z+r GEMM (one pass over own stripe) ----
        #pragma unroll 1
        for (int b = 0; b < NB; ++b) {
            unsigned long long az0 = 0, az1 = 0, ar0 = 0, ar1 = 0;
            const float* hrow = &asm_h[b * AST + w * 32];
            #pragma unroll
            for (int q = 0; q < 8; ++q) {
                ulonglong2 hv = *(const ulonglong2*)(hrow + q * 4);
                fma2(az0, hv.x, uz2[2 * q]);
                fma2(az1, hv.y, uz2[2 * q + 1]);
                fma2(ar0, hv.x, ur2[2 * q]);
                fma2(ar1, hv.y, ur2[2 * q + 1]);
            }
            red_z[(w * 16 + b) * 32 + l] = add2(az0, az1);
            red_r[(w * 16 + b) * 32 + l] = add2(ar0, ar1);
        }
        __syncthreads();   // S1: partials + all h staging visible CTA-wide

        // ---- C: r reduce, publish tagged rh rows {w, w+8} immediately ----
        float hd0, hd1;
        {
            unsigned long long s0 = 0, s1 = 0;
            #pragma unroll
            for (int ww = 0; ww < 8; ++ww) {
                s0 = add2(s0, red_r[(ww * 16 + w) * 32 + l]);
                s1 = add2(s1, red_r[(ww * 16 + w + 8) * 32 + l]);
            }
            float r0 = sigmoid_(fold2(s0) + xr0);
            float r1 = sigmoid_(fold2(s1) + xr1);
            hd0 = asm_h[w * AST + j];
            hd1 = asm_h[(w + 8) * AST + j];
            st_tag(&g_rh64[p][grp][w][j],     tagpack(r0 * hd0, (unsigned)(t + 1)));
            st_tag(&g_rh64[p][grp][w + 8][j], tagpack(r1 * hd1, (unsigned)(t + 1)));
        }

        // ---- D: z reduce (fills rh propagation latency) ----
        float zv0, zv1;
        {
            unsigned long long s0 = 0, s1 = 0;
            #pragma unroll
            for (int ww = 0; ww < 8; ++ww) {
                s0 = add2(s0, red_z[(ww * 16 + w) * 32 + l]);
                s1 = add2(s1, red_z[(ww * 16 + w + 8) * 32 + l]);
            }
            zv0 = sigmoid_(fold2(s0) + xz0);
            zv1 = sigmoid_(fold2(s1) + xz1);
        }

        // ---- E: tagged spin-gather of rh(t) slice (tag == t+1) ----
        gather16(&g_rh64[p][grp][0][gcol], (unsigned)(t + 1), &asm_rh[gcol]);
        __syncwarp();

        // ---- F: h GEMM (partials into red_h; no hazard with C/D) ----
        #pragma unroll 1
        for (int b = 0; b < NB; ++b) {
            unsigned long long ah0 = 0, ah1 = 0;
            const float* hrow = &asm_rh[b * AST + w * 32];
            #pragma unroll
            for (int q = 0; q < 8; ++q) {
                ulonglong2 hv = *(const ulonglong2*)(hrow + q * 4);
                fma2(ah0, hv.x, uh2[2 * q]);
                fma2(ah1, hv.y, uh2[2 * q + 1]);
            }
            red_h[(w * 16 + b) * 32 + l] = add2(ah0, ah1);
        }
        __syncthreads();   // S3

        // ---- H: h reduce, combine, publish tagged pre-decayed h(t+1) ----
        float h0, h1;
        {
            unsigned long long s0 = 0, s1 = 0;
            #pragma unroll
            for (int ww = 0; ww < 8; ++ww) {
                s0 = add2(s0, red_h[(ww * 16 + w) * 32 + l]);
                s1 = add2(s1, red_h[(ww * 16 + w + 8) * 32 + l]);
            }
            float hp0 = tanh_(fold2(s0) + xh0);
            float hp1 = tanh_(fold2(s1) + xh1);
            h0 = (1.f - zv0) * hd0 + zv0 * hp0;
            h1 = (1.f - zv1) * hd1 + zv1 * hp1;
            if (more) {
                st_tag(&g_h64[(t + 1) & 1][grp][w][j],
                       tagpack(h0 * decn0, (unsigned)(t + 1)));
                st_tag(&g_h64[(t + 1) & 1][grp][w + 8][j],
                       tagpack(h1 * decn1, (unsigned)(t + 1)));
            }
        }

        // ---- I: outputs + next-step x prefetch (off critical path) ----
        out[m0 * 256 + j] = h0;
        out[m1 * 256 + j] = h1;
        if (more) {
            xz0 = g_xp[(m0 + 1) * 256 + j];          xz1 = g_xp[(m1 + 1) * 256 + j];
            xr0 = g_xp[MH + (m0 + 1) * 256 + j];     xr1 = g_xp[MH + (m1 + 1) * 256 + j];
            xh0 = g_xp[2 * MH + (m0 + 1) * 256 + j]; xh1 = g_xp[2 * MH + (m1 + 1) * 256 + j];
        }
    }
}

// ================= launch =================
extern "C" void kernel_launch(void* const* d_in, const int* /*in_sizes*/, int /*n_in*/,
                              void* d_out, int /*out_size*/)
{
    const float* x      = (const float*)d_in[0];
    const float* hdecay = (const float*)d_in[1];
    const float* Wr = (const float*)d_in[2];
    const float* Wz = (const float*)d_in[3];
    const float* Wh = (const float*)d_in[4];
    const float* Ur = (const float*)d_in[5];
    const float* Uz = (const float*)d_in[6];
    const float* Uh = (const float*)d_in[7];
    const float* br = (const float*)d_in[8];
    const float* bz = (const float*)d_in[9];
    const float* bh = (const float*)d_in[10];
    float* out = (float*)d_out;

    // smem: 2 asm arrays (16*264 floats = 16896B each) + 3 reduce arrays (32KB each)
    constexpr int SMEM_SCAN = 2 * (NB * AST * 4) + 3 * 32768;   // 131840 B
    cudaFuncSetAttribute(scan_kernel, cudaFuncAttributeMaxDynamicSharedMemorySize, SMEM_SCAN);

    proj_kernel<<<dim3(MTOT / 128, H_ / 128, 3), 256>>>(x, Wz, Wr, Wh, bz, br, bh);
    reset_kernel<<<(TAGWORDS + 255) / 256, 256>>>();
    scan_kernel<<<NBG * NC, 256, SMEM_SCAN>>>(Uz, Ur, Uh, hdecay, out);
}